// round 15
// baseline (speedup 1.0000x reference)
#include <cuda_runtime.h>

#define TB   64      // batch
#define TT   512     // timesteps
#define DIN  64
#define DM   512     // d_model
#define DOUT 64
#define NCB  16      // column blocks
#define NC   32      // cols per CTA
#define NBB  8       // batch blocks
#define NB   8       // batches per CTA
#define GB   128     // persistent grid
#define NT   256     // threads per k_seq CTA (8 warps)
#define HP   516     // padded row length (conflict-free layouts)

typedef unsigned long long u64;

// ---- device scratch (allocation-free) --------------------------------------
__device__ float g_pre0 [TT * TB * DM];   // [t][b][j]
__device__ float g_h1all[TT * TB * DM];   // [t][b][j]
__device__ float g_h0   [2 * TB * DM];    // ping-pong h0
__device__ float g_h1   [2 * TB * DM];    // ping-pong h1
// phase-separated monotonic counters -> race-free by construction
__device__ unsigned int g_barA[NBB];
__device__ unsigned int g_barB[NBB];

// packed fp32x2 FMA — kept ONLY in k_pre (measured win there, loss in k_seq)
__device__ __forceinline__ u64 ffma2(u64 a, u64 b, u64 c) {
    u64 d;
    asm("fma.rn.f32x2 %0, %1, %2, %3;" : "=l"(d) : "l"(a), "l"(b), "l"(c));
    return d;
}
__device__ __forceinline__ float f2sum(u64 v) {
    float x, y;
    asm("mov.b64 {%0,%1}, %2;" : "=f"(x), "=f"(y) : "l"(v));
    return x + y;
}

// ---------------------------------------------------------------------------
// k_pre: pre0 = x@Wih0 + bih0 + bhh0 (measured ~110us). Also resets barrier
// counters and zeros parity-1 hidden state.
// ---------------------------------------------------------------------------
__global__ void __launch_bounds__(256, 1)
k_pre(const float* __restrict__ data, const float* __restrict__ Wih0,
      const float* __restrict__ bih0, const float* __restrict__ bhh0)
{
    extern __shared__ float sm[];
    float*  xs = sm;                          // [64][64]
    float2* Wp = (float2*)(sm + TB * DIN);    // [32 k2][512 j]
    float*  bs = sm + TB * DIN + 2 * 32 * DM; // [512]

    const int t = blockIdx.x, tid = threadIdx.x;
    if (t == 0 && tid < NBB) { g_barA[tid] = 0u; g_barB[tid] = 0u; }
    if (t < 128) {
        int i = t * 256 + tid;
        g_h0[TB * DM + i] = 0.0f;
        g_h1[TB * DM + i] = 0.0f;
    }

    for (int i = tid; i < TB * DIN; i += 256) {
        int b = i >> 6, k = i & 63;
        xs[b * DIN + k] = data[(b * TT + t) * DIN + k];
    }
    for (int i = tid; i < 32 * DM; i += 256) {
        int k2 = i >> 9, j = i & 511;
        Wp[i] = make_float2(Wih0[(2 * k2) * DM + j], Wih0[(2 * k2 + 1) * DM + j]);
    }
    for (int i = tid; i < DM; i += 256) bs[i] = bih0[i] + bhh0[i];
    __syncthreads();

    const int j0 = tid;
    for (int g = 0; g < 8; g++) {
        u64 acc[2][8];
        #pragma unroll
        for (int c = 0; c < 2; c++)
            #pragma unroll
            for (int b = 0; b < 8; b++) acc[c][b] = 0ULL;
        #pragma unroll 8
        for (int k2 = 0; k2 < 32; k2++) {
            u64 w0 = *(const u64*)&Wp[k2 * DM + j0];
            u64 w1 = *(const u64*)&Wp[k2 * DM + j0 + 256];
            #pragma unroll
            for (int b = 0; b < 8; b++) {
                u64 h = *(const u64*)&xs[(g * 8 + b) * DIN + 2 * k2];
                acc[0][b] = ffma2(h, w0, acc[0][b]);
                acc[1][b] = ffma2(h, w1, acc[1][b]);
            }
        }
        #pragma unroll
        for (int b = 0; b < 8; b++) {
            int bg = g * 8 + b;
            g_pre0[(t * TB + bg) * DM + j0]       = f2sum(acc[0][b]) + bs[j0];
            g_pre0[(t * TB + bg) * DM + j0 + 256] = f2sum(acc[1][b]) + bs[j0 + 256];
        }
    }
}

// ---------------------------------------------------------------------------
// arrive: bar.sync (cross-thread HB) + thread0 release-add.
// wait: thread0 acquire-polls one counter, then bar.sync. Phase-separated.
// ---------------------------------------------------------------------------
__device__ __forceinline__ void arrive(unsigned int* ctr)
{
    __syncthreads();
    if (threadIdx.x == 0)
        asm volatile("red.release.gpu.global.add.u32 [%0], %1;"
                     :: "l"(ctr), "r"(1u) : "memory");
}
__device__ __forceinline__ void waitcnt(unsigned int* ctr, unsigned int tgt)
{
    if (threadIdx.x == 0) {
        unsigned int v;
        do {
            asm volatile("ld.acquire.gpu.global.u32 %0, [%1];"
                         : "=r"(v) : "l"(ctr) : "memory");
        } while (v < tgt);
    }
    __syncthreads();
}

// stage 8 batch rows (4096 floats) global -> padded smem [8][HP], L2-coherent
__device__ __forceinline__ void stage_pad(float* dst, const float* src, int tid)
{
    const float4* s = (const float4*)src;
    #pragma unroll
    for (int j = 0; j < 4; j++) {
        int idx = tid + NT * j;       // 0..1023 float4 units
        int bq  = idx >> 7;           // batch row 0..7
        int kq  = idx & 127;          // float4 col unit
        *(float4*)&dst[bq * HP + kq * 4] = __ldcg(&s[idx]);
    }
}

// ---------------------------------------------------------------------------
// k_seq: 512 steps, 128 persistent CTAs x 256 thr, smem 231168 B.
// Lane (w,lc): cw = 4w+(lc&3), b = lc>>2 -> ONE output per GEMM, full k=512.
// No cross-warp reduction. Wt[c][HP] transposed slices; h staged [8][HP].
// Pipelined: wait A_t hidden behind h1_prev@Whh1; wait B_t behind phase-1 epilogue.
// ---------------------------------------------------------------------------
__global__ void __launch_bounds__(NT, 1)
k_seq(const float* __restrict__ Whh0, const float* __restrict__ Wih1,
      const float* __restrict__ bih1, const float* __restrict__ Whh1,
      const float* __restrict__ bhh1)
{
    extern __shared__ float sm[];
    float* Wt0 = sm;                    // [32][HP] Whh0 slice (transposed)
    float* Wt1 = sm + 32 * HP;          // Wih1 slice
    float* Wt2 = sm + 2 * 32 * HP;      // Whh1 slice
    float* h0s = sm + 3 * 32 * HP;      // [8][HP]
    float* h1s = h0s + NB * HP;         // [8][HP]

    const int tid = threadIdx.x;
    const int cb  = blockIdx.x & (NCB - 1);
    const int bb  = blockIdx.x >> 4;
    const int c0  = cb * NC, b0 = bb * NB;
    unsigned int* barA = &g_barA[bb];
    unsigned int* barB = &g_barB[bb];

    // transpose-stage weight slices (coalesced reads, one-time scattered STS)
    for (int idx = tid; idx < 32 * DM; idx += NT) {
        int k = idx >> 5, c = idx & 31;
        int d = c * HP + k;
        int g = k * DM + c0 + c;
        Wt0[d] = Whh0[g];
        Wt1[d] = Wih1[g];
        Wt2[d] = Whh1[g];
    }

    const int w  = tid >> 5, lc = tid & 31;
    const int c  = lc & 3,   b  = lc >> 2;
    const int cw = w * 4 + c;           // local col 0..31
    const int cg = c0 + cw, bg = b0 + b;
    const int ho = b * HP;              // h row offset
    const int wo = cw * HP;             // W row offset
    const float bias1 = __ldg(&bih1[cg]) + __ldg(&bhh1[cg]);

    // prime h1s with zeros (parity-1 buffer, zeroed by k_pre)
    stage_pad(h1s, g_h1 + TB * DM + b0 * DM, tid);
    __syncthreads();

    // ---- prologue: h0_0 = tanh(pre0[0]) ----
    g_h0[bg * DM + cg] = tanhf(__ldg(&g_pre0[bg * DM + cg]));
    arrive(barA);                                         // A_0

    for (int t = 0; t < TT; t++) {
        const int p = t & 1;
        const bool last = (t == TT - 1);

        // 1. acc2 = h1_{t-1} @ Whh1   (hides wait A_t) — dual chains
        float a0 = 0.0f, a1 = 0.0f;
        #pragma unroll 8
        for (int k = 0; k < DM; k += 8) {
            float4 hA = *(const float4*)&h1s[ho + k];
            float4 wA = *(const float4*)&Wt2[wo + k];
            float4 hB = *(const float4*)&h1s[ho + k + 4];
            float4 wB = *(const float4*)&Wt2[wo + k + 4];
            a0 = fmaf(hA.x, wA.x, a0); a0 = fmaf(hA.y, wA.y, a0);
            a0 = fmaf(hA.z, wA.z, a0); a0 = fmaf(hA.w, wA.w, a0);
            a1 = fmaf(hB.x, wB.x, a1); a1 = fmaf(hB.y, wB.y, a1);
            a1 = fmaf(hB.z, wB.z, a1); a1 = fmaf(hB.w, wB.w, a1);
        }
        float acc2 = a0 + a1;

        // 2. wait A_t; stage h0_t
        waitcnt(barA, (unsigned)(t + 1) * NCB);
        stage_pad(h0s, g_h0 + p * TB * DM + b0 * DM, tid);
        __syncthreads();

        // pre for t+1 (clamped at last; value unused then) — hoisted LDG
        int tn = last ? t : t + 1;
        float pre = __ldg(&g_pre0[(tn * TB + bg) * DM + cg]);

        // 3. fused pass over h0_t: u += Wih1.h0, v += Whh0.h0
        float u0 = 0.0f, u1 = 0.0f, v0 = 0.0f, v1 = 0.0f;
        #pragma unroll 4
        for (int k = 0; k < DM; k += 8) {
            float4 hA = *(const float4*)&h0s[ho + k];
            float4 hB = *(const float4*)&h0s[ho + k + 4];
            float4 pA = *(const float4*)&Wt1[wo + k];
            float4 pB = *(const float4*)&Wt1[wo + k + 4];
            float4 qA = *(const float4*)&Wt0[wo + k];
            float4 qB = *(const float4*)&Wt0[wo + k + 4];
            u0 = fmaf(hA.x, pA.x, u0); u0 = fmaf(hA.y, pA.y, u0);
            u0 = fmaf(hA.z, pA.z, u0); u0 = fmaf(hA.w, pA.w, u0);
            v0 = fmaf(hA.x, qA.x, v0); v0 = fmaf(hA.y, qA.y, v0);
            v0 = fmaf(hA.z, qA.z, v0); v0 = fmaf(hA.w, qA.w, v0);
            u1 = fmaf(hB.x, pB.x, u1); u1 = fmaf(hB.y, pB.y, u1);
            u1 = fmaf(hB.z, pB.z, u1); u1 = fmaf(hB.w, pB.w, u1);
            v1 = fmaf(hB.x, qB.x, v1); v1 = fmaf(hB.y, qB.y, v1);
            v1 = fmaf(hB.z, qB.z, v1); v1 = fmaf(hB.w, qB.w, v1);
        }

        // 4. h1_t direct from registers; arrive B_t
        {
            float h1n = tanhf(acc2 + u0 + u1 + bias1);
            int gi = bg * DM + cg;
            g_h1[p * TB * DM + gi]    = h1n;
            g_h1all[t * TB * DM + gi] = h1n;
        }
        arrive(barB);                                     // B_t

        if (!last) {
            // 5. h0_{t+1} direct; arrive A_{t+1}
            g_h0[(p ^ 1) * TB * DM + bg * DM + cg] = tanhf(v0 + v1 + pre);
            arrive(barA);                                 // A_{t+1}

            // 6. wait B_t (skew-only); stage h1_t
            waitcnt(barB, (unsigned)(t + 1) * NCB);
            stage_pad(h1s, g_h1 + p * TB * DM + b0 * DM, tid);
            __syncthreads();
        }
    }
}

// ---------------------------------------------------------------------------
// k_out: out[b][t][:] = h1all[t][b][:] @ Wout + bout
// ---------------------------------------------------------------------------
__global__ void __launch_bounds__(256, 1)
k_out(const float* __restrict__ Wout, const float* __restrict__ bout,
      float* __restrict__ out)
{
    extern __shared__ float sm[];
    float* Ws = sm;                 // [512][64]
    float* hs = Ws + DM * DOUT;     // [64][128] k-chunk

    const int t = blockIdx.x, tid = threadIdx.x;
    for (int i = tid; i < DM * DOUT; i += 256) Ws[i] = Wout[i];

    const int j  = tid & 63;
    const int bq = tid >> 6;
    float acc[16];
    #pragma unroll
    for (int i = 0; i < 16; i++) acc[i] = 0.0f;

    for (int kc = 0; kc < 4; kc++) {
        __syncthreads();
        for (int idx = tid; idx < TB * 128; idx += 256) {
            int b = idx >> 7, kk = idx & 127;
            hs[idx] = g_h1all[(t * TB + b) * DM + kc * 128 + kk];
        }
        __syncthreads();
        for (int kk = 0; kk < 128; kk++) {
            float wv = Ws[(kc * 128 + kk) * DOUT + j];
            #pragma unroll
            for (int i = 0; i < 16; i++)
                acc[i] = fmaf(hs[(bq * 16 + i) * 128 + kk], wv, acc[i]);
        }
    }
    float bj = bout[j];
    #pragma unroll
    for (int i = 0; i < 16; i++) {
        int b = bq * 16 + i;
        out[(b * TT + t) * DOUT + j] = acc[i] + bj;
    }
}

// ---------------------------------------------------------------------------
extern "C" void kernel_launch(void* const* d_in, const int* in_sizes, int n_in,
                              void* d_out, int out_size)
{
    const float* data = (const float*)d_in[0];
    const float* Wih0 = (const float*)d_in[1];
    const float* bih0 = (const float*)d_in[2];
    const float* Whh0 = (const float*)d_in[3];
    const float* bhh0 = (const float*)d_in[4];
    const float* Wih1 = (const float*)d_in[5];
    const float* bih1 = (const float*)d_in[6];
    const float* Whh1 = (const float*)d_in[7];
    const float* bhh1 = (const float*)d_in[8];
    const float* Wout = (const float*)d_in[9];
    const float* bout = (const float*)d_in[10];
    float* out = (float*)d_out;

    cudaFuncSetAttribute(k_pre, cudaFuncAttributeMaxDynamicSharedMemorySize, 149504);
    cudaFuncSetAttribute(k_seq, cudaFuncAttributeMaxDynamicSharedMemorySize, 231168);
    cudaFuncSetAttribute(k_out, cudaFuncAttributeMaxDynamicSharedMemorySize, 163840);

    k_pre<<<TT, 256, 149504>>>(data, Wih0, bih0, bhh0);
    k_seq<<<GB, NT, 231168>>>(Whh0, Wih1, bih1, Whh1, bhh1);
    k_out<<<TT, 256, 163840>>>(Wout, bout, out);
}